// round 7
// baseline (speedup 1.0000x reference)
#include <cuda_runtime.h>

#define BATCH 8
#define NPTS  8192
#define NCENT 512

// ---------------- scratch (device globals: no allocations allowed) ----------
__device__ float g_support[BATCH * 64 * NPTS];
__device__ float g_h1[BATCH * 128 * NPTS];
__device__ float g_h2[BATCH * 256 * NPTS];
__device__ float g_feat[BATCH * 256 * NPTS];
__device__ float g_kbuf[BATCH * 256 * NPTS];
__device__ float g_vbuf[BATCH * 256 * NPTS];
__device__ float g_qbuf[BATCH * 256 * NCENT];
__device__ float g_cent[BATCH * 256 * NCENT];
__device__ float g_logits[BATCH * NCENT * NPTS];
__device__ float g_attpart[BATCH * 4 * 256 * NCENT];
__device__ float g_att[BATCH * 256 * NCENT];
__device__ int   g_idx[BATCH * NCENT];
__device__ float g_bns1[128], g_bnh1[128];
__device__ float g_bns2[256], g_bnh2[256];
// FPS cross-CTA coordination (reset by fps_init each call)
__device__ unsigned long long g_best[BATCH * 8];   // 8-slot ring per batch
__device__ unsigned int       g_count[BATCH * 2];  // monotonic, per parity

// ---------------- init: zero FPS coordination state --------------------------
__global__ void fps_init_kernel()
{
    int t = threadIdx.x;
    if (t < BATCH * 8) g_best[t] = 0ull;
    if (t < BATCH * 2) g_count[t] = 0u;
}

// ---------------- build support = concat(xyz, point_features) ---------------
__global__ void __launch_bounds__(256) support_kernel(
    const float* __restrict__ xyz, const float* __restrict__ pf)
{
    int total = BATCH * 64 * (NPTS / 4);
    for (int v = blockIdx.x * blockDim.x + threadIdx.x; v < total; v += gridDim.x * blockDim.x) {
        int b = v >> 17;              // 64*2048 float4 per batch
        int rem = v & 131071;
        int c = rem >> 11;            // 2048 float4 per channel
        int nv = rem & 2047;
        float4 f;
        if (c < 3)
            f = reinterpret_cast<const float4*>(xyz + ((long long)b * 3 + c) * NPTS)[nv];
        else
            f = reinterpret_cast<const float4*>(pf + ((long long)b * 61 + (c - 3)) * NPTS)[nv];
        reinterpret_cast<float4*>(g_support)[v] = f;
    }
}

// ---------------- FPS: 8 batches x 16 CTAs, gmem barrier (no clusters) ------
// Each thread owns one point's 64 channels in registers. Per-point distance is
// accumulated in DOUBLE then rounded ONCE to float32 (= correctly-rounded
// float32 of the true distance, order-independent), mimicking the reference's
// float32 value modulo its own reduction-order noise. Min-carry and argmax
// stay in float32. Argmax via packed u64 (dist_bits<<32 | ~idx) atomicMax into
// an 8-deep ring slot; barrier = monotonic per-(batch,parity) counter.
// Max dist wins, ties -> lowest index (jnp.argmax).
__global__ void __launch_bounds__(512, 1) fps_kernel(const int* __restrict__ far0)
{
    __shared__ float cent[64];
    __shared__ unsigned long long warp_best[16];
    __shared__ int s_far;

    int rank = blockIdx.x & 15;
    int b = blockIdx.x >> 4;
    int t = threadIdx.x;
    const float* sb = g_support + (long long)b * 64 * NPTS;
    int myn = (rank << 9) + t;

    float p[64];
#pragma unroll
    for (int c = 0; c < 64; ++c) p[c] = sb[(c << 13) + myn];

    float distance = 1e10f;
    int far = far0[b];
    if (rank == 0 && t == 0) g_idx[b * NCENT] = far;

    unsigned long long* best = g_best + b * 8;
    volatile unsigned int* cnt = (volatile unsigned int*)(g_count + b * 2);

    for (int m = 0; m < NCENT - 1; ++m) {
        if (t < 64) cent[t] = sb[(t << 13) + far];
        __syncthreads();
        double dd = 0.0;
#pragma unroll
        for (int c = 0; c < 64; ++c) {
            double df = (double)p[c] - (double)cent[c];
            dd = fma(df, df, dd);
        }
        float d = (float)dd;                  // correctly-rounded fp32 distance
        distance = fminf(distance, d);
        unsigned long long key =
            ((unsigned long long)__float_as_uint(distance) << 32)
            | (unsigned long long)(0xFFFFFFFFu - (unsigned)myn);
#pragma unroll
        for (int o = 16; o > 0; o >>= 1) {
            unsigned long long ok = __shfl_xor_sync(0xFFFFFFFFu, key, o);
            key = (ok > key) ? ok : key;
        }
        if ((t & 31) == 0) warp_best[t >> 5] = key;
        __syncthreads();
        if (t == 0) {
            unsigned long long kk = warp_best[0];
#pragma unroll
            for (int w = 1; w < 16; ++w) {
                unsigned long long o2 = warp_best[w];
                kk = (o2 > kk) ? o2 : kk;
            }
            int slot = m & 7;
            int par = m & 1;
            atomicMax(best + slot, kk);
            __threadfence();                          // release best
            atomicAdd((unsigned int*)(g_count + b * 2 + par), 1u);
            unsigned target = 16u * (unsigned)(m / 2 + 1);
            while (cnt[par] < target) { }             // monotonic -> safe
            __threadfence();                          // acquire best
            unsigned long long win = best[slot];
            int f = (int)(0xFFFFFFFFu - (unsigned)(win & 0xFFFFFFFFull));
            s_far = f;
            if (rank == 0) {
                g_idx[b * NCENT + m + 1] = f;
                best[(m + 4) & 7] = 0ull;             // ring reset (see header)
            }
        }
        __syncthreads();
        far = s_far;
    }
}

// ---------------- generic SGEMM, 128x128 tile, 8x8 per thread ---------------
// AMODE 0: A[M,K] row-major.  AMODE 1: A[K,M].
// BMODE 0: B[K,N] (optional per-k bnscale/bnshift + leaky-relu on load).
// BMODE 1: B[N,K].
// C = scale*(A*B) + bias[row] + addbuf. ksplit: raw partials per z-slab.
template<int AMODE, int BMODE>
__global__ void __launch_bounds__(256) sgemm_kernel(
    const float* __restrict__ A, const float* __restrict__ Bm, float* __restrict__ C,
    int Md, int Nd, int Kd,
    long long sA, long long sB, long long sC,
    const float* __restrict__ bias, const float* __restrict__ addbuf,
    const float* __restrict__ bnscale, const float* __restrict__ bnshift,
    float scale, int ksplit)
{
    __shared__ float As[16][128];
    __shared__ float Bs[16][128];
    int bz = blockIdx.z;
    int batch = bz / ksplit;
    int ks = bz - batch * ksplit;
    int kchunk = Kd / ksplit;
    int k0 = ks * kchunk;
    int k1 = k0 + kchunk;
    const float* Ab = A + (long long)batch * sA;
    const float* Bb = Bm + (long long)batch * sB;
    float* Cb = C + (long long)bz * sC;
    int bm0 = blockIdx.y * 128;
    int bn0 = blockIdx.x * 128;
    int t = threadIdx.x;
    int row0 = (t >> 4) << 3;
    int col0 = (t & 15) << 3;
    float acc[8][8];
#pragma unroll
    for (int i = 0; i < 8; ++i)
#pragma unroll
        for (int j = 0; j < 8; ++j) acc[i][j] = 0.f;

    for (int kt = k0; kt < k1; kt += 16) {
#pragma unroll
        for (int it = 0; it < 2; ++it) {
            int v = t + it * 256;
            if (AMODE == 0) {
                int r = v >> 2;
                int kv = (v & 3) << 2;
                const float4 f = *reinterpret_cast<const float4*>(
                    Ab + (long long)(bm0 + r) * Kd + kt + kv);
                As[kv + 0][r] = f.x; As[kv + 1][r] = f.y;
                As[kv + 2][r] = f.z; As[kv + 3][r] = f.w;
            } else {
                int kk = v >> 5;
                int mv = (v & 31) << 2;
                *reinterpret_cast<float4*>(&As[kk][mv]) =
                    *reinterpret_cast<const float4*>(Ab + (long long)(kt + kk) * Md + bm0 + mv);
            }
        }
#pragma unroll
        for (int it = 0; it < 2; ++it) {
            int v = t + it * 256;
            if (BMODE == 0) {
                int kk = v >> 5;
                int nv = (v & 31) << 2;
                float4 f = *reinterpret_cast<const float4*>(
                    Bb + (long long)(kt + kk) * Nd + bn0 + nv);
                if (bnscale) {
                    float s = bnscale[kt + kk], sh = bnshift[kt + kk];
                    f.x = f.x * s + sh; f.y = f.y * s + sh;
                    f.z = f.z * s + sh; f.w = f.w * s + sh;
                    f.x = f.x > 0.f ? f.x : 0.2f * f.x;
                    f.y = f.y > 0.f ? f.y : 0.2f * f.y;
                    f.z = f.z > 0.f ? f.z : 0.2f * f.z;
                    f.w = f.w > 0.f ? f.w : 0.2f * f.w;
                }
                *reinterpret_cast<float4*>(&Bs[kk][nv]) = f;
            } else {
                int n = v >> 2;
                int kv = (v & 3) << 2;
                const float4 f = *reinterpret_cast<const float4*>(
                    Bb + (long long)(bn0 + n) * Kd + kt + kv);
                Bs[kv + 0][n] = f.x; Bs[kv + 1][n] = f.y;
                Bs[kv + 2][n] = f.z; Bs[kv + 3][n] = f.w;
            }
        }
        __syncthreads();
#pragma unroll
        for (int kk = 0; kk < 16; ++kk) {
            float ra[8], rb[8];
            *reinterpret_cast<float4*>(&ra[0]) = *reinterpret_cast<const float4*>(&As[kk][row0]);
            *reinterpret_cast<float4*>(&ra[4]) = *reinterpret_cast<const float4*>(&As[kk][row0 + 4]);
            *reinterpret_cast<float4*>(&rb[0]) = *reinterpret_cast<const float4*>(&Bs[kk][col0]);
            *reinterpret_cast<float4*>(&rb[4]) = *reinterpret_cast<const float4*>(&Bs[kk][col0 + 4]);
#pragma unroll
            for (int i = 0; i < 8; ++i)
#pragma unroll
                for (int j = 0; j < 8; ++j)
                    acc[i][j] = fmaf(ra[i], rb[j], acc[i][j]);
        }
        __syncthreads();
    }

#pragma unroll
    for (int i = 0; i < 8; ++i) {
        int r = bm0 + row0 + i;
        float bv = bias ? bias[r] : 0.f;
#pragma unroll
        for (int jv = 0; jv < 2; ++jv) {
            int cidx = bn0 + col0 + (jv << 2);
            float4 o;
            o.x = acc[i][jv * 4 + 0] * scale + bv;
            o.y = acc[i][jv * 4 + 1] * scale + bv;
            o.z = acc[i][jv * 4 + 2] * scale + bv;
            o.w = acc[i][jv * 4 + 3] * scale + bv;
            if (addbuf) {
                const float4 a4 = *reinterpret_cast<const float4*>(
                    addbuf + (long long)batch * sC + (long long)r * Nd + cidx);
                o.x += a4.x; o.y += a4.y; o.z += a4.z; o.w += a4.w;
            }
            *reinterpret_cast<float4*>(Cb + (long long)r * Nd + cidx) = o;
        }
    }
}

// ---------------- BatchNorm (train-mode) per-channel affine -----------------
__global__ void __launch_bounds__(256) bn_stats_kernel(
    const float* __restrict__ x, const float* __restrict__ gamma,
    const float* __restrict__ beta, float* __restrict__ scale,
    float* __restrict__ shift, int Cd)
{
    __shared__ float rs[8], rq[8];
    int c = blockIdx.x;
    int t = threadIdx.x;
    float s = 0.f, q = 0.f;
    for (int b = 0; b < BATCH; ++b) {
        const float4* p = reinterpret_cast<const float4*>(x + ((long long)b * Cd + c) * NPTS);
        for (int v = t; v < NPTS / 4; v += 256) {
            float4 f = p[v];
            s += f.x + f.y + f.z + f.w;
            q += f.x * f.x + f.y * f.y + f.z * f.z + f.w * f.w;
        }
    }
#pragma unroll
    for (int o = 16; o; o >>= 1) {
        s += __shfl_xor_sync(0xFFFFFFFFu, s, o);
        q += __shfl_xor_sync(0xFFFFFFFFu, q, o);
    }
    if ((t & 31) == 0) { rs[t >> 5] = s; rq[t >> 5] = q; }
    __syncthreads();
    if (t == 0) {
        float S = 0.f, Q = 0.f;
#pragma unroll
        for (int w = 0; w < 8; ++w) { S += rs[w]; Q += rq[w]; }
        const float inv = 1.f / (float)(BATCH * NPTS);
        float mean = S * inv;
        float var = Q * inv - mean * mean;
        float rstd = rsqrtf(var + 1e-5f);
        float g = gamma[c];
        scale[c] = rstd * g;
        shift[c] = beta[c] - mean * rstd * g;
    }
}

// ---------------- gather centroids (feat) and new_xyz -----------------------
__global__ void __launch_bounds__(256) gather_kernel(
    const float* __restrict__ xyz, float* __restrict__ out_xyz)
{
    int v = blockIdx.x * blockDim.x + threadIdx.x;
    if (v < BATCH * 256 * NCENT) {
        int b = v >> 17;
        int rem = v & 131071;
        int c = rem >> 9;
        int m = rem & 511;
        int id = g_idx[b * NCENT + m];
        g_cent[v] = g_feat[((long long)b * 256 + c) * NPTS + id];
    }
    if (v < BATCH * 3 * NCENT) {
        int b = v / (3 * NCENT);
        int rem = v - b * 3 * NCENT;
        int c = rem >> 9;
        int m = rem & 511;
        int id = g_idx[b * NCENT + m];
        out_xyz[v] = xyz[((long long)b * 3 + c) * NPTS + id];
    }
}

// ---------------- softmax over last dim, rows in registers ------------------
__global__ void __launch_bounds__(256) softmax_kernel()
{
    __shared__ float red[8];
    long long row = blockIdx.x;
    float4* p = reinterpret_cast<float4*>(g_logits + row * NPTS);
    int t = threadIdx.x;
    float4 v[8];
#pragma unroll
    for (int i = 0; i < 8; ++i) v[i] = p[t + (i << 8)];
    float mx = -1e30f;
#pragma unroll
    for (int i = 0; i < 8; ++i)
        mx = fmaxf(mx, fmaxf(fmaxf(v[i].x, v[i].y), fmaxf(v[i].z, v[i].w)));
#pragma unroll
    for (int o = 16; o; o >>= 1) mx = fmaxf(mx, __shfl_xor_sync(0xFFFFFFFFu, mx, o));
    if ((t & 31) == 0) red[t >> 5] = mx;
    __syncthreads();
#pragma unroll
    for (int w = 0; w < 8; ++w) mx = fmaxf(mx, red[w]);
    __syncthreads();
    float s = 0.f;
#pragma unroll
    for (int i = 0; i < 8; ++i) {
        v[i].x = __expf(v[i].x - mx); v[i].y = __expf(v[i].y - mx);
        v[i].z = __expf(v[i].z - mx); v[i].w = __expf(v[i].w - mx);
        s += v[i].x + v[i].y + v[i].z + v[i].w;
    }
#pragma unroll
    for (int o = 16; o; o >>= 1) s += __shfl_xor_sync(0xFFFFFFFFu, s, o);
    if ((t & 31) == 0) red[t >> 5] = s;
    __syncthreads();
    s = 0.f;
#pragma unroll
    for (int w = 0; w < 8; ++w) s += red[w];
    float inv = 1.f / s;
#pragma unroll
    for (int i = 0; i < 8; ++i) {
        v[i].x *= inv; v[i].y *= inv; v[i].z *= inv; v[i].w *= inv;
        p[t + (i << 8)] = v[i];
    }
}

// ---------------- split-K reduction (4 slabs) -------------------------------
__global__ void __launch_bounds__(256) reduce4_kernel()
{
    int v = blockIdx.x * blockDim.x + threadIdx.x;   // float4 index
    int total = BATCH * 256 * NCENT / 4;             // 262144
    if (v >= total) return;
    int b = v >> 15;                                  // 32768 f4 per batch
    int i = v & 32767;
    const float4* pp = reinterpret_cast<const float4*>(g_attpart);
    float4 s = pp[((long long)b * 4 + 0) * 32768 + i];
#pragma unroll
    for (int ks = 1; ks < 4; ++ks) {
        float4 x = pp[((long long)b * 4 + ks) * 32768 + i];
        s.x += x.x; s.y += x.y; s.z += x.z; s.w += x.w;
    }
    reinterpret_cast<float4*>(g_att)[v] = s;
}

// ---------------- host launcher ---------------------------------------------
static float* sym(const void* s) {
    void* p = nullptr;
    cudaGetSymbolAddress(&p, (const void*)s);
    return (float*)p;
}

extern "C" void kernel_launch(void* const* d_in, const int* in_sizes, int n_in,
                              void* d_out, int out_size)
{
    const float* xyz = (const float*)d_in[0];
    const float* pf  = (const float*)d_in[1];
    const float* w1  = (const float*)d_in[2];
    const float* b1  = (const float*)d_in[3];
    const float* g1  = (const float*)d_in[4];
    const float* be1 = (const float*)d_in[5];
    const float* w2  = (const float*)d_in[6];
    const float* b2  = (const float*)d_in[7];
    const float* g2  = (const float*)d_in[8];
    const float* be2 = (const float*)d_in[9];
    const float* w3  = (const float*)d_in[10];
    const float* b3  = (const float*)d_in[11];
    const float* wq  = (const float*)d_in[12];
    const float* wk  = (const float*)d_in[13];
    const float* wv  = (const float*)d_in[14];
    const float* wo  = (const float*)d_in[15];
    const int*   far0 = (const int*)d_in[16];
    float* out = (float*)d_out;

    float* p_sup  = sym(g_support);
    float* p_h1   = sym(g_h1);
    float* p_h2   = sym(g_h2);
    float* p_feat = sym(g_feat);
    float* p_k    = sym(g_kbuf);
    float* p_v    = sym(g_vbuf);
    float* p_q    = sym(g_qbuf);
    float* p_cent = sym(g_cent);
    float* p_log  = sym(g_logits);
    float* p_ap   = sym(g_attpart);
    float* p_att  = sym(g_att);
    float* p_s1   = sym(g_bns1);
    float* p_sh1  = sym(g_bnh1);
    float* p_s2   = sym(g_bns2);
    float* p_sh2  = sym(g_bnh2);

    // 0. reset FPS coordination state (device globals persist across replays)
    fps_init_kernel<<<1, 64>>>();

    // 1. support = concat(xyz, point_features)
    support_kernel<<<1024, 256>>>(xyz, pf);

    // 2. FPS: 128 persistent CTAs (16 per batch), gmem barriers, no clusters
    fps_kernel<<<128, 512>>>(far0);

    // 3. h1 = w1 @ support + b1
    sgemm_kernel<0, 0><<<dim3(64, 1, 8), 256>>>(
        w1, p_sup, p_h1, 128, NPTS, 64,
        0LL, 64LL * NPTS, 128LL * NPTS,
        b1, nullptr, nullptr, nullptr, 1.f, 1);

    // 4. BN1 stats
    bn_stats_kernel<<<128, 256>>>(p_h1, g1, be1, p_s1, p_sh1, 128);

    // 5. h2 = w2 @ lrelu(bn(h1)) + b2   (BN+LReLU fused into B load)
    sgemm_kernel<0, 0><<<dim3(64, 2, 8), 256>>>(
        w2, p_h1, p_h2, 256, NPTS, 128,
        0LL, 128LL * NPTS, 256LL * NPTS,
        b2, nullptr, p_s1, p_sh1, 1.f, 1);

    // 6. BN2 stats
    bn_stats_kernel<<<256, 256>>>(p_h2, g2, be2, p_s2, p_sh2, 256);

    // 7. feat = w3 @ lrelu(bn(h2)) + b3
    sgemm_kernel<0, 0><<<dim3(64, 2, 8), 256>>>(
        w3, p_h2, p_feat, 256, NPTS, 256,
        0LL, 256LL * NPTS, 256LL * NPTS,
        b3, nullptr, p_s2, p_sh2, 1.f, 1);

    // 8. gather centroids + new_xyz (new_xyz = first 12288 floats of out)
    gather_kernel<<<4096, 256>>>(xyz, out);

    // 9/10. k = wk @ feat ; v = wv @ feat
    sgemm_kernel<0, 0><<<dim3(64, 2, 8), 256>>>(
        wk, p_feat, p_k, 256, NPTS, 256,
        0LL, 256LL * NPTS, 256LL * NPTS,
        nullptr, nullptr, nullptr, nullptr, 1.f, 1);
    sgemm_kernel<0, 0><<<dim3(64, 2, 8), 256>>>(
        wv, p_feat, p_v, 256, NPTS, 256,
        0LL, 256LL * NPTS, 256LL * NPTS,
        nullptr, nullptr, nullptr, nullptr, 1.f, 1);

    // 11. q = wq @ centroids
    sgemm_kernel<0, 0><<<dim3(4, 2, 8), 256>>>(
        wq, p_cent, p_q, 256, NCENT, 256,
        0LL, 256LL * NCENT, 256LL * NCENT,
        nullptr, nullptr, nullptr, nullptr, 1.f, 1);

    // 12. logits = (q^T k) / 16
    sgemm_kernel<1, 0><<<dim3(64, 4, 8), 256>>>(
        p_q, p_k, p_log, NCENT, NPTS, 256,
        256LL * NCENT, 256LL * NPTS, (long long)NCENT * NPTS,
        nullptr, nullptr, nullptr, nullptr, 0.0625f, 1);

    // 13. softmax over N
    softmax_kernel<<<BATCH * NCENT, 256>>>();

    // 14. att1 = probs @ v^T  (split-K 4)
    sgemm_kernel<0, 1><<<dim3(4, 2, 32), 256>>>(
        p_v, p_log, p_ap, 256, NCENT, NPTS,
        256LL * NPTS, (long long)NCENT * NPTS, 256LL * NCENT,
        nullptr, nullptr, nullptr, nullptr, 1.f, 4);

    // 15. reduce split-K partials
    reduce4_kernel<<<1024, 256>>>();

    // 16. out2 = centroids + wo @ att1 (written into out + 12288)
    sgemm_kernel<0, 0><<<dim3(4, 2, 8), 256>>>(
        wo, p_att, out + BATCH * 3 * NCENT, 256, NCENT, 256,
        0LL, 256LL * NCENT, 256LL * NCENT,
        nullptr, p_cent, nullptr, nullptr, 1.f, 1);
}

// round 9
// speedup vs baseline: 1.0635x; 1.0635x over previous
#include <cuda_runtime.h>
#include <cstdint>

#define BATCH 8
#define NPTS  8192
#define NCENT 512
#define KSPLIT_PV 8

// ---------------- scratch (device globals: no allocations allowed) ----------
__device__ float g_support[BATCH * 64 * NPTS];
__device__ float g_h1[BATCH * 128 * NPTS];
__device__ float g_h2[BATCH * 256 * NPTS];
__device__ float g_feat[BATCH * 256 * NPTS];
__device__ float g_kbuf[BATCH * 256 * NPTS];
__device__ float g_vbuf[BATCH * 256 * NPTS];
__device__ float g_qbuf[BATCH * 256 * NCENT];
__device__ float g_cent[BATCH * 256 * NCENT];
__device__ float g_logits[BATCH * NCENT * NPTS];
__device__ float g_attpart[BATCH * KSPLIT_PV * 256 * NCENT];
__device__ float g_att[BATCH * 256 * NCENT];
__device__ int   g_idx[BATCH * NCENT];
__device__ float g_bns1[128], g_bnh1[128];
__device__ float g_bns2[256], g_bnh2[256];
// FPS cross-CTA coordination (reset by fps_init each call)
__device__ unsigned long long g_best[BATCH * 8];   // 8-slot ring per batch
__device__ unsigned int       g_count[BATCH * 2];  // monotonic, per parity

__device__ __forceinline__ void cp_async16(uint32_t dst, const void* src) {
    asm volatile("cp.async.cg.shared.global [%0], [%1], 16;\n" :: "r"(dst), "l"(src));
}
__device__ __forceinline__ void cp_commit() {
    asm volatile("cp.async.commit_group;\n");
}
__device__ __forceinline__ void cp_wait_all() {
    asm volatile("cp.async.wait_group 0;\n" ::: "memory");
}

// ---------------- init: zero FPS coordination state --------------------------
__global__ void fps_init_kernel()
{
    int t = threadIdx.x;
    if (t < BATCH * 8) g_best[t] = 0ull;
    if (t < BATCH * 2) g_count[t] = 0u;
}

// ---------------- build support = concat(xyz, point_features) ---------------
__global__ void __launch_bounds__(256) support_kernel(
    const float* __restrict__ xyz, const float* __restrict__ pf)
{
    int total = BATCH * 64 * (NPTS / 4);
    for (int v = blockIdx.x * blockDim.x + threadIdx.x; v < total; v += gridDim.x * blockDim.x) {
        int b = v >> 17;
        int rem = v & 131071;
        int c = rem >> 11;
        int nv = rem & 2047;
        float4 f;
        if (c < 3)
            f = reinterpret_cast<const float4*>(xyz + ((long long)b * 3 + c) * NPTS)[nv];
        else
            f = reinterpret_cast<const float4*>(pf + ((long long)b * 61 + (c - 3)) * NPTS)[nv];
        reinterpret_cast<float4*>(g_support)[v] = f;
    }
}

// ---------------- FPS (unchanged from passing round 7) ----------------------
__global__ void __launch_bounds__(512, 1) fps_kernel(const int* __restrict__ far0)
{
    __shared__ float cent[64];
    __shared__ unsigned long long warp_best[16];
    __shared__ int s_far;

    int rank = blockIdx.x & 15;
    int b = blockIdx.x >> 4;
    int t = threadIdx.x;
    const float* sb = g_support + (long long)b * 64 * NPTS;
    int myn = (rank << 9) + t;

    float p[64];
#pragma unroll
    for (int c = 0; c < 64; ++c) p[c] = sb[(c << 13) + myn];

    float distance = 1e10f;
    int far = far0[b];
    if (rank == 0 && t == 0) g_idx[b * NCENT] = far;

    unsigned long long* best = g_best + b * 8;
    volatile unsigned int* cnt = (volatile unsigned int*)(g_count + b * 2);

    for (int m = 0; m < NCENT - 1; ++m) {
        if (t < 64) cent[t] = sb[(t << 13) + far];
        __syncthreads();
        double dd = 0.0;
#pragma unroll
        for (int c = 0; c < 64; ++c) {
            double df = (double)p[c] - (double)cent[c];
            dd = fma(df, df, dd);
        }
        float d = (float)dd;                  // correctly-rounded fp32 distance
        distance = fminf(distance, d);
        unsigned long long key =
            ((unsigned long long)__float_as_uint(distance) << 32)
            | (unsigned long long)(0xFFFFFFFFu - (unsigned)myn);
#pragma unroll
        for (int o = 16; o > 0; o >>= 1) {
            unsigned long long ok = __shfl_xor_sync(0xFFFFFFFFu, key, o);
            key = (ok > key) ? ok : key;
        }
        if ((t & 31) == 0) warp_best[t >> 5] = key;
        __syncthreads();
        if (t == 0) {
            unsigned long long kk = warp_best[0];
#pragma unroll
            for (int w = 1; w < 16; ++w) {
                unsigned long long o2 = warp_best[w];
                kk = (o2 > kk) ? o2 : kk;
            }
            int slot = m & 7;
            int par = m & 1;
            atomicMax(best + slot, kk);
            __threadfence();
            atomicAdd((unsigned int*)(g_count + b * 2 + par), 1u);
            unsigned target = 16u * (unsigned)(m / 2 + 1);
            while (cnt[par] < target) { }
            __threadfence();
            unsigned long long win = best[slot];
            int f = (int)(0xFFFFFFFFu - (unsigned)(win & 0xFFFFFFFFull));
            s_far = f;
            if (rank == 0) {
                g_idx[b * NCENT + m + 1] = f;
                best[(m + 4) & 7] = 0ull;
            }
        }
        __syncthreads();
        far = s_far;
    }
}

// ---------------- pipelined SGEMM, 128x128 tile, 8x8/thread, 2-stage --------
// AMODE 0: A[M,K] row-major (register-staged transpose into As[k][m]).
// AMODE 1: A[K,M]            (cp.async direct into As[k][m]).
// BMODE 0: B[K,N]            (cp.async direct into Bs[k][n]).
// BMODE 1: B[N,K]            (register-staged transpose into Bs[k][n]).
// C = scale*(A*B) + bias[row] + addbuf. ksplit: raw partials per z-slab.
template<int AMODE, int BMODE>
__global__ void __launch_bounds__(256, 2) sgemm_kernel(
    const float* __restrict__ A, const float* __restrict__ Bm, float* __restrict__ C,
    int Md, int Nd, int Kd,
    long long sA, long long sB, long long sC,
    const float* __restrict__ bias, const float* __restrict__ addbuf,
    float scale, int ksplit)
{
    __shared__ float As[2][16][128];
    __shared__ float Bs[2][16][128];
    int bz = blockIdx.z;
    int batch = bz / ksplit;
    int ks = bz - batch * ksplit;
    int kchunk = Kd / ksplit;
    int k0 = ks * kchunk;
    int ntiles = kchunk >> 4;
    const float* Ab = A + (long long)batch * sA;
    const float* Bb = Bm + (long long)batch * sB;
    float* Cb = C + (long long)bz * sC;
    int bm0 = blockIdx.y * 128;
    int bn0 = blockIdx.x * 128;
    int t = threadIdx.x;
    int row0 = (t >> 4) << 3;
    int col0 = (t & 15) << 3;

    uint32_t sAs = (uint32_t)__cvta_generic_to_shared(&As[0][0][0]);
    uint32_t sBs = (uint32_t)__cvta_generic_to_shared(&Bs[0][0][0]);

    float4 fa0, fa1, fb0, fb1;

    auto issueA = [&](int bb, int kt) {
        if (AMODE == 0) {
            int v0 = t, v1 = t + 256;
            fa0 = *reinterpret_cast<const float4*>(
                Ab + (long long)(bm0 + (v0 >> 2)) * Kd + kt + ((v0 & 3) << 2));
            fa1 = *reinterpret_cast<const float4*>(
                Ab + (long long)(bm0 + (v1 >> 2)) * Kd + kt + ((v1 & 3) << 2));
        } else {
#pragma unroll
            for (int i2 = 0; i2 < 2; ++i2) {
                int v = t + i2 * 256;
                int kk = v >> 5, mv = (v & 31) << 2;
                cp_async16(sAs + (uint32_t)((((bb << 11) | (kk << 7) | mv)) << 2),
                           Ab + (long long)(kt + kk) * Md + bm0 + mv);
            }
        }
    };
    auto storeA = [&](int bb) {
        if (AMODE == 0) {
            int v0 = t, r0 = v0 >> 2, k0v = (v0 & 3) << 2;
            As[bb][k0v + 0][r0] = fa0.x; As[bb][k0v + 1][r0] = fa0.y;
            As[bb][k0v + 2][r0] = fa0.z; As[bb][k0v + 3][r0] = fa0.w;
            int v1 = t + 256, r1 = v1 >> 2, k1v = (v1 & 3) << 2;
            As[bb][k1v + 0][r1] = fa1.x; As[bb][k1v + 1][r1] = fa1.y;
            As[bb][k1v + 2][r1] = fa1.z; As[bb][k1v + 3][r1] = fa1.w;
        }
    };
    auto issueB = [&](int bb, int kt) {
        if (BMODE == 0) {
#pragma unroll
            for (int i2 = 0; i2 < 2; ++i2) {
                int v = t + i2 * 256;
                int kk = v >> 5, nv = (v & 31) << 2;
                cp_async16(sBs + (uint32_t)((((bb << 11) | (kk << 7) | nv)) << 2),
                           Bb + (long long)(kt + kk) * Nd + bn0 + nv);
            }
        } else {
            int v0 = t, v1 = t + 256;
            fb0 = *reinterpret_cast<const float4*>(
                Bb + (long long)(bn0 + (v0 >> 2)) * Kd + kt + ((v0 & 3) << 2));
            fb1 = *reinterpret_cast<const float4*>(
                Bb + (long long)(bn0 + (v1 >> 2)) * Kd + kt + ((v1 & 3) << 2));
        }
    };
    auto storeB = [&](int bb) {
        if (BMODE == 1) {
            int v0 = t, n0 = v0 >> 2, k0v = (v0 & 3) << 2;
            Bs[bb][k0v + 0][n0] = fb0.x; Bs[bb][k0v + 1][n0] = fb0.y;
            Bs[bb][k0v + 2][n0] = fb0.z; Bs[bb][k0v + 3][n0] = fb0.w;
            int v1 = t + 256, n1 = v1 >> 2, k1v = (v1 & 3) << 2;
            Bs[bb][k1v + 0][n1] = fb1.x; Bs[bb][k1v + 1][n1] = fb1.y;
            Bs[bb][k1v + 2][n1] = fb1.z; Bs[bb][k1v + 3][n1] = fb1.w;
        }
    };

    float acc[8][8];
#pragma unroll
    for (int i = 0; i < 8; ++i)
#pragma unroll
        for (int j = 0; j < 8; ++j) acc[i][j] = 0.f;

    // prologue: stage tile 0 into buffer 0
    issueA(0, k0); issueB(0, k0);
    storeA(0); storeB(0);
    cp_commit();
    cp_wait_all();
    __syncthreads();

    int buf = 0;
    for (int it = 0; it < ntiles; ++it) {
        bool hn = (it + 1 < ntiles);
        if (hn) {
            int ktn = k0 + ((it + 1) << 4);
            issueA(buf ^ 1, ktn);
            issueB(buf ^ 1, ktn);
            cp_commit();
        }
        const float (*Asb)[128] = As[buf];
        const float (*Bsb)[128] = Bs[buf];
#pragma unroll
        for (int kk = 0; kk < 16; ++kk) {
            float ra[8], rb[8];
            *reinterpret_cast<float4*>(&ra[0]) = *reinterpret_cast<const float4*>(&Asb[kk][row0]);
            *reinterpret_cast<float4*>(&ra[4]) = *reinterpret_cast<const float4*>(&Asb[kk][row0 + 4]);
            *reinterpret_cast<float4*>(&rb[0]) = *reinterpret_cast<const float4*>(&Bsb[kk][col0]);
            *reinterpret_cast<float4*>(&rb[4]) = *reinterpret_cast<const float4*>(&Bsb[kk][col0 + 4]);
#pragma unroll
            for (int i = 0; i < 8; ++i)
#pragma unroll
                for (int j = 0; j < 8; ++j)
                    acc[i][j] = fmaf(ra[i], rb[j], acc[i][j]);
        }
        if (hn) {
            storeA(buf ^ 1);
            storeB(buf ^ 1);
            cp_wait_all();
            __syncthreads();
            buf ^= 1;
        }
    }

#pragma unroll
    for (int i = 0; i < 8; ++i) {
        int r = bm0 + row0 + i;
        float bv = bias ? bias[r] : 0.f;
#pragma unroll
        for (int jv = 0; jv < 2; ++jv) {
            int cidx = bn0 + col0 + (jv << 2);
            float4 o;
            o.x = acc[i][jv * 4 + 0] * scale + bv;
            o.y = acc[i][jv * 4 + 1] * scale + bv;
            o.z = acc[i][jv * 4 + 2] * scale + bv;
            o.w = acc[i][jv * 4 + 3] * scale + bv;
            if (addbuf) {
                const float4 a4 = *reinterpret_cast<const float4*>(
                    addbuf + (long long)batch * sC + (long long)r * Nd + cidx);
                o.x += a4.x; o.y += a4.y; o.z += a4.z; o.w += a4.w;
            }
            *reinterpret_cast<float4*>(Cb + (long long)r * Nd + cidx) = o;
        }
    }
}

// ---------------- BatchNorm (train-mode) per-channel affine -----------------
__global__ void __launch_bounds__(256) bn_stats_kernel(
    const float* __restrict__ x, const float* __restrict__ gamma,
    const float* __restrict__ beta, float* __restrict__ scale,
    float* __restrict__ shift, int Cd)
{
    __shared__ float rs[8], rq[8];
    int c = blockIdx.x;
    int t = threadIdx.x;
    float s = 0.f, q = 0.f;
    for (int b = 0; b < BATCH; ++b) {
        const float4* p = reinterpret_cast<const float4*>(x + ((long long)b * Cd + c) * NPTS);
        for (int v = t; v < NPTS / 4; v += 256) {
            float4 f = p[v];
            s += f.x + f.y + f.z + f.w;
            q += f.x * f.x + f.y * f.y + f.z * f.z + f.w * f.w;
        }
    }
#pragma unroll
    for (int o = 16; o; o >>= 1) {
        s += __shfl_xor_sync(0xFFFFFFFFu, s, o);
        q += __shfl_xor_sync(0xFFFFFFFFu, q, o);
    }
    if ((t & 31) == 0) { rs[t >> 5] = s; rq[t >> 5] = q; }
    __syncthreads();
    if (t == 0) {
        float S = 0.f, Q = 0.f;
#pragma unroll
        for (int w = 0; w < 8; ++w) { S += rs[w]; Q += rq[w]; }
        const float inv = 1.f / (float)(BATCH * NPTS);
        float mean = S * inv;
        float var = Q * inv - mean * mean;
        float rstd = rsqrtf(var + 1e-5f);
        float g = gamma[c];
        scale[c] = rstd * g;
        shift[c] = beta[c] - mean * rstd * g;
    }
}

// ---------------- BN affine + LeakyReLU, in-place ---------------------------
__global__ void __launch_bounds__(256) bn_apply_kernel(
    float* __restrict__ x, const float* __restrict__ scale,
    const float* __restrict__ shift, int Cd)
{
    int total = BATCH * Cd * (NPTS / 4);
    for (int v = blockIdx.x * blockDim.x + threadIdx.x; v < total; v += gridDim.x * blockDim.x) {
        int c = (v >> 11) % Cd;     // 2048 float4 per channel row
        float s = scale[c], sh = shift[c];
        float4 f = reinterpret_cast<float4*>(x)[v];
        f.x = f.x * s + sh; f.y = f.y * s + sh;
        f.z = f.z * s + sh; f.w = f.w * s + sh;
        f.x = f.x > 0.f ? f.x : 0.2f * f.x;
        f.y = f.y > 0.f ? f.y : 0.2f * f.y;
        f.z = f.z > 0.f ? f.z : 0.2f * f.z;
        f.w = f.w > 0.f ? f.w : 0.2f * f.w;
        reinterpret_cast<float4*>(x)[v] = f;
    }
}

// ---------------- gather centroids (feat) and new_xyz -----------------------
__global__ void __launch_bounds__(256) gather_kernel(
    const float* __restrict__ xyz, float* __restrict__ out_xyz)
{
    int v = blockIdx.x * blockDim.x + threadIdx.x;
    if (v < BATCH * 256 * NCENT) {
        int b = v >> 17;
        int rem = v & 131071;
        int c = rem >> 9;
        int m = rem & 511;
        int id = g_idx[b * NCENT + m];
        g_cent[v] = g_feat[((long long)b * 256 + c) * NPTS + id];
    }
    if (v < BATCH * 3 * NCENT) {
        int b = v / (3 * NCENT);
        int rem = v - b * 3 * NCENT;
        int c = rem >> 9;
        int m = rem & 511;
        int id = g_idx[b * NCENT + m];
        out_xyz[v] = xyz[((long long)b * 3 + c) * NPTS + id];
    }
}

// ---------------- softmax over last dim, rows in registers ------------------
__global__ void __launch_bounds__(256) softmax_kernel()
{
    __shared__ float red[8];
    long long row = blockIdx.x;
    float4* p = reinterpret_cast<float4*>(g_logits + row * NPTS);
    int t = threadIdx.x;
    float4 v[8];
#pragma unroll
    for (int i = 0; i < 8; ++i) v[i] = p[t + (i << 8)];
    float mx = -1e30f;
#pragma unroll
    for (int i = 0; i < 8; ++i)
        mx = fmaxf(mx, fmaxf(fmaxf(v[i].x, v[i].y), fmaxf(v[i].z, v[i].w)));
#pragma unroll
    for (int o = 16; o; o >>= 1) mx = fmaxf(mx, __shfl_xor_sync(0xFFFFFFFFu, mx, o));
    if ((t & 31) == 0) red[t >> 5] = mx;
    __syncthreads();
#pragma unroll
    for (int w = 0; w < 8; ++w) mx = fmaxf(mx, red[w]);
    __syncthreads();
    float s = 0.f;
#pragma unroll
    for (int i = 0; i < 8; ++i) {
        v[i].x = __expf(v[i].x - mx); v[i].y = __expf(v[i].y - mx);
        v[i].z = __expf(v[i].z - mx); v[i].w = __expf(v[i].w - mx);
        s += v[i].x + v[i].y + v[i].z + v[i].w;
    }
#pragma unroll
    for (int o = 16; o; o >>= 1) s += __shfl_xor_sync(0xFFFFFFFFu, s, o);
    if ((t & 31) == 0) red[t >> 5] = s;
    __syncthreads();
    s = 0.f;
#pragma unroll
    for (int w = 0; w < 8; ++w) s += red[w];
    float inv = 1.f / s;
#pragma unroll
    for (int i = 0; i < 8; ++i) {
        v[i].x *= inv; v[i].y *= inv; v[i].z *= inv; v[i].w *= inv;
        p[t + (i << 8)] = v[i];
    }
}

// ---------------- split-K reduction (KSPLIT_PV slabs) -----------------------
__global__ void __launch_bounds__(256) reduceK_kernel()
{
    int v = blockIdx.x * blockDim.x + threadIdx.x;   // float4 index
    int total = BATCH * 256 * NCENT / 4;             // 262144
    if (v >= total) return;
    int b = v >> 15;                                  // 32768 f4 per batch
    int i = v & 32767;
    const float4* pp = reinterpret_cast<const float4*>(g_attpart);
    float4 s = pp[((long long)b * KSPLIT_PV + 0) * 32768 + i];
#pragma unroll
    for (int ks = 1; ks < KSPLIT_PV; ++ks) {
        float4 x = pp[((long long)b * KSPLIT_PV + ks) * 32768 + i];
        s.x += x.x; s.y += x.y; s.z += x.z; s.w += x.w;
    }
    reinterpret_cast<float4*>(g_att)[v] = s;
}

// ---------------- host launcher ---------------------------------------------
static float* sym(const void* s) {
    void* p = nullptr;
    cudaGetSymbolAddress(&p, (const void*)s);
    return (float*)p;
}

extern "C" void kernel_launch(void* const* d_in, const int* in_sizes, int n_in,
                              void* d_out, int out_size)
{
    const float* xyz = (const float*)d_in[0];
    const float* pf  = (const float*)d_in[1];
    const float* w1  = (const float*)d_in[2];
    const float* b1  = (const float*)d_in[3];
    const float* g1  = (const float*)d_in[4];
    const float* be1 = (const float*)d_in[5];
    const float* w2  = (const float*)d_in[6];
    const float* b2  = (const float*)d_in[7];
    const float* g2  = (const float*)d_in[8];
    const float* be2 = (const float*)d_in[9];
    const float* w3  = (const float*)d_in[10];
    const float* b3  = (const float*)d_in[11];
    const float* wq  = (const float*)d_in[12];
    const float* wk  = (const float*)d_in[13];
    const float* wv  = (const float*)d_in[14];
    const float* wo  = (const float*)d_in[15];
    const int*   far0 = (const int*)d_in[16];
    float* out = (float*)d_out;

    float* p_sup  = sym(g_support);
    float* p_h1   = sym(g_h1);
    float* p_h2   = sym(g_h2);
    float* p_feat = sym(g_feat);
    float* p_k    = sym(g_kbuf);
    float* p_v    = sym(g_vbuf);
    float* p_q    = sym(g_qbuf);
    float* p_cent = sym(g_cent);
    float* p_log  = sym(g_logits);
    float* p_ap   = sym(g_attpart);
    float* p_att  = sym(g_att);
    float* p_s1   = sym(g_bns1);
    float* p_sh1  = sym(g_bnh1);
    float* p_s2   = sym(g_bns2);
    float* p_sh2  = sym(g_bnh2);

    // 0. reset FPS coordination state (device globals persist across replays)
    fps_init_kernel<<<1, 64>>>();

    // 1. support = concat(xyz, point_features)
    support_kernel<<<1024, 256>>>(xyz, pf);

    // 2. FPS: 128 persistent CTAs (16 per batch), gmem barriers
    fps_kernel<<<128, 512>>>(far0);

    // 3. h1 = w1 @ support + b1
    sgemm_kernel<0, 0><<<dim3(64, 1, 8), 256>>>(
        w1, p_sup, p_h1, 128, NPTS, 64,
        0LL, 64LL * NPTS, 128LL * NPTS,
        b1, nullptr, 1.f, 1);

    // 4. BN1 stats + apply (in-place lrelu(bn(h1)))
    bn_stats_kernel<<<128, 256>>>(p_h1, g1, be1, p_s1, p_sh1, 128);
    bn_apply_kernel<<<2048, 256>>>(p_h1, p_s1, p_sh1, 128);

    // 5. h2 = w2 @ h1' + b2
    sgemm_kernel<0, 0><<<dim3(64, 2, 8), 256>>>(
        w2, p_h1, p_h2, 256, NPTS, 128,
        0LL, 128LL * NPTS, 256LL * NPTS,
        b2, nullptr, 1.f, 1);

    // 6. BN2 stats + apply
    bn_stats_kernel<<<256, 256>>>(p_h2, g2, be2, p_s2, p_sh2, 256);
    bn_apply_kernel<<<4096, 256>>>(p_h2, p_s2, p_sh2, 256);

    // 7. feat = w3 @ h2' + b3
    sgemm_kernel<0, 0><<<dim3(64, 2, 8), 256>>>(
        w3, p_h2, p_feat, 256, NPTS, 256,
        0LL, 256LL * NPTS, 256LL * NPTS,
        b3, nullptr, 1.f, 1);

    // 8. gather centroids + new_xyz (new_xyz = first 12288 floats of out)
    gather_kernel<<<4096, 256>>>(xyz, out);

    // 9/10. k = wk @ feat ; v = wv @ feat
    sgemm_kernel<0, 0><<<dim3(64, 2, 8), 256>>>(
        wk, p_feat, p_k, 256, NPTS, 256,
        0LL, 256LL * NPTS, 256LL * NPTS,
        nullptr, nullptr, 1.f, 1);
    sgemm_kernel<0, 0><<<dim3(64, 2, 8), 256>>>(
        wv, p_feat, p_v, 256, NPTS, 256,
        0LL, 256LL * NPTS, 256LL * NPTS,
        nullptr, nullptr, 1.f, 1);

    // 11. q = wq @ centroids
    sgemm_kernel<0, 0><<<dim3(4, 2, 8), 256>>>(
        wq, p_cent, p_q, 256, NCENT, 256,
        0LL, 256LL * NCENT, 256LL * NCENT,
        nullptr, nullptr, 1.f, 1);

    // 12. logits = (q^T k) / 16
    sgemm_kernel<1, 0><<<dim3(64, 4, 8), 256>>>(
        p_q, p_k, p_log, NCENT, NPTS, 256,
        256LL * NCENT, 256LL * NPTS, (long long)NCENT * NPTS,
        nullptr, nullptr, 0.0625f, 1);

    // 13. softmax over N
    softmax_kernel<<<BATCH * NCENT, 256>>>();

    // 14. att1 = probs @ v^T  (split-K)
    sgemm_kernel<0, 1><<<dim3(4, 2, 8 * KSPLIT_PV), 256>>>(
        p_v, p_log, p_ap, 256, NCENT, NPTS,
        256LL * NPTS, (long long)NCENT * NPTS, 256LL * NCENT,
        nullptr, nullptr, 1.f, KSPLIT_PV);

    // 15. reduce split-K partials
    reduceK_kernel<<<1024, 256>>>();

    // 16. out2 = centroids + wo @ att1 (written into out + 12288)
    sgemm_kernel<0, 0><<<dim3(4, 2, 8), 256>>>(
        wo, p_att, out + BATCH * 3 * NCENT, 256, NCENT, 256,
        0LL, 256LL * NCENT, 256LL * NCENT,
        nullptr, p_cent, 1.f, 1);
}